// round 8
// baseline (speedup 1.0000x reference)
#include <cuda_runtime.h>
#include <cuda_fp16.h>
#include <cstdint>

#define N_SAMP 4096
#define V 256
#define VM1 255
#define NH 64
#define NCOLS (V * NH)   // 16384
#define TILES 4096       // 32 m-blocks x 128 gc-tiles (m-major)
#define GRID_MAIN 296
#define CHUNK 14         // ceil(4096/296)

__device__ __half g_Ah[N_SAMP * V];   // data as fp16 [4096][256]
__device__ __half g_Bh[NCOLS * V];    // B^T: [gc][j]
__device__ float  g_gate[NCOLS];      // neurons[h,c]*w_out[c,h]

__device__ __forceinline__ uint32_t smem_u32(const void* p) {
    uint32_t a;
    asm("{ .reg .u64 t; cvta.to.shared.u64 t, %1; cvt.u32.u64 %0, t; }" : "=r"(a) : "l"(p));
    return a;
}
__device__ __forceinline__ float tanh_fast(float x) {
    float y; asm("tanh.approx.f32 %0, %1;" : "=f"(y) : "f"(x)); return y;
}
#define CP_ASYNC16(dst_u32, src_ptr) \
    asm volatile("cp.async.cg.shared.global [%0], [%1], 16;" :: "r"(dst_u32), "l"(src_ptr) : "memory")
#define CP_COMMIT() asm volatile("cp.async.commit_group;" ::: "memory")

// ---------------------------------------------------------------------------
// Merged prep (unchanged from R7)
// ---------------------------------------------------------------------------
__global__ __launch_bounds__(256) void prep_kernel(
    const float4* __restrict__ data4,
    const float*  __restrict__ adj,
    const float*  __restrict__ neurons,
    const float*  __restrict__ w_in,
    const float*  __restrict__ w_out,
    float4* __restrict__ out_adj4)
{
    __shared__ float s[64][65];
    __shared__ float adjv[64];
    const int tid = threadIdx.x;

    if (blockIdx.x < 1024) {
        int idx = blockIdx.x * 256 + tid;
        if (idx < (N_SAMP * V) / 4) {
            float4 v = data4[idx];
            __half2* dst = (__half2*)(g_Ah + idx * 4);
            dst[0] = __floats2half2_rn(v.x, v.y);
            dst[1] = __floats2half2_rn(v.z, v.w);
        }
        if (idx < (V * V) / 4) out_adj4[idx] = ((const float4*)adj)[idx];
        if (idx < NCOLS / 4) {
            int gc = idx * 4;
            int c = gc >> 6, h = gc & 63;
            float4 g;
            g.x = neurons[(h + 0) * V + c] * w_out[gc + 0];
            g.y = neurons[(h + 1) * V + c] * w_out[gc + 1];
            g.z = neurons[(h + 2) * V + c] * w_out[gc + 2];
            g.w = neurons[(h + 3) * V + c] * w_out[gc + 3];
            *(float4*)(g_gate + gc) = g;
        }
    } else {
        const int bid = blockIdx.x - 1024;
        const int c   = bid >> 2;
        const int jb  = bid & 3;
        const int h   = tid & 63;
        const int kk4 = tid >> 6;

        if (tid < 64) {
            int j = jb * 64 + tid;
            adjv[tid] = (j == c) ? 0.0f : adj[j * V + c];
        }
        #pragma unroll
        for (int jj0 = 0; jj0 < 64; jj0 += 4) {
            int jj = jj0 + kk4;
            int j  = jb * 64 + jj;
            float w = 0.0f;
            if (j != c) {
                int k = j - (j > c ? 1 : 0);
                w = w_in[(c * VM1 + k) * NH + h];
            }
            s[jj][h] = w;
        }
        __syncthreads();
        #pragma unroll
        for (int h0 = 0; h0 < 64; h0 += 4) {
            int hh = h0 + (tid >> 6);
            int jj = tid & 63;
            float w = s[jj][hh] * adjv[jj];
            g_Bh[(c * 64 + hh) * V + jb * 64 + jj] = __float2half_rn(w);
        }
    }
}

// ---------------------------------------------------------------------------
// Persistent fused GEMM, A-resident in SMEM per m-block run.
// SMEM: A 64KB (full K) + B double buffer 2x16KB = 96KB -> 2 CTAs/SM.
// ---------------------------------------------------------------------------
#define A_BYTES 65536
#define B_STAGE 16384
#define SMEM_TOTAL (A_BYTES + 2 * B_STAGE)   // 98304

__device__ __forceinline__ void prefetchB(uint32_t sB, int gc0, int k0,
                                          int ldr, int ldq) {
    #pragma unroll
    for (int i = 0; i < 8; i++) {
        int r = ldr + i * 16;
        uint32_t dsw = (uint32_t)(r * 128 + ((ldq ^ (r & 7)) << 4));
        CP_ASYNC16(sB + dsw, g_Bh + (gc0 + r) * V + k0 + ldq * 8);
    }
}

__global__ __launch_bounds__(128, 2)
void fused_mma_kernel(const float* __restrict__ b_in,
                      const float* __restrict__ b_out,
                      float* __restrict__ out) {
    extern __shared__ __align__(16) char smem[];
    const uint32_t sbA = smem_u32(smem);
    const uint32_t sbB = sbA + A_BYTES;

    const int tid  = threadIdx.x;
    const int wid  = tid >> 5;
    const int lane = tid & 31;
    const int wr   = wid & 1;
    const int wc   = wid >> 1;
    const int ldr  = tid >> 3;
    const int ldq  = tid & 7;
    const int g    = lane >> 2;
    const int tig  = lane & 3;

    const int lo = blockIdx.x * CHUNK;
    if (lo >= TILES) return;
    const int hi = (lo + CHUNK < TILES) ? lo + CHUNK : TILES;

    int i = lo;
    while (i < hi) {
        const int mb = i >> 7;
        const int m0 = mb << 7;
        const int jend = ((mb + 1) << 7) < hi ? ((mb + 1) << 7) : hi;
        const int nst = (jend - i) * 4;

        // ---- flush pipeline; load A (full K) + B stage 0 ----
        asm volatile("cp.async.wait_group 0;" ::: "memory");
        __syncthreads();
        #pragma unroll
        for (int c2 = 0; c2 < 32; c2++) {
            int id = tid + c2 * 128;
            int r = id >> 5, q = id & 31;
            uint32_t dsw = (uint32_t)(r * 512 + ((q ^ (r & 7)) << 4));
            CP_ASYNC16(sbA + dsw, g_Ah + (m0 + r) * V + q * 8);
        }
        prefetchB(sbB, (i & 127) * 128, 0, ldr, ldq);
        CP_COMMIT();
        asm volatile("cp.async.wait_group 0;" ::: "memory");
        __syncthreads();

        for (int j = i; j < jend; j++) {
            const int s_base = (j - i) * 4;
            const int gc0 = (j & 127) * 128;

            float d[4][8][4];
            #pragma unroll
            for (int mt = 0; mt < 4; mt++)
                #pragma unroll
                for (int nt = 0; nt < 8; nt++)
                    #pragma unroll
                    for (int v = 0; v < 4; v++) d[mt][nt][v] = 0.0f;

            #pragma unroll
            for (int t = 0; t < 4; t++) {
                const int s = s_base + t;
                if (s + 1 < nst) {
                    const int j2 = (t == 3) ? j + 1 : j;
                    const int t2 = (t + 1) & 3;
                    prefetchB(sbB + (uint32_t)(((s + 1) & 1) * B_STAGE),
                              (j2 & 127) * 128, t2 * 64, ldr, ldq);
                    CP_COMMIT();
                    asm volatile("cp.async.wait_group 1;" ::: "memory");
                } else {
                    asm volatile("cp.async.wait_group 0;" ::: "memory");
                }
                __syncthreads();

                const uint32_t sB = sbB + (uint32_t)((s & 1) * B_STAGE);

                #pragma unroll
                for (int ks = 0; ks < 4; ks++) {
                    uint32_t a[4][4];
                    #pragma unroll
                    for (int mt = 0; mt < 4; mt++) {
                        int r = wr * 64 + mt * 16 + (lane & 15);
                        int q = t * 8 + ks * 2 + (lane >> 4);
                        uint32_t addr = sbA + r * 512 + ((q ^ (r & 7)) << 4);
                        asm volatile("ldmatrix.sync.aligned.m8n8.x4.shared.b16 {%0,%1,%2,%3}, [%4];"
                            : "=r"(a[mt][0]), "=r"(a[mt][1]), "=r"(a[mt][2]), "=r"(a[mt][3])
                            : "r"(addr));
                    }
                    uint32_t bf[8][2];
                    #pragma unroll
                    for (int p = 0; p < 4; p++) {
                        int r = wc * 64 + p * 16 + (lane & 7) + ((lane >> 4) << 3);
                        int q = ks * 2 + ((lane >> 3) & 1);
                        uint32_t addr = sB + r * 128 + ((q ^ (r & 7)) << 4);
                        uint32_t r0, r1, r2, r3;
                        asm volatile("ldmatrix.sync.aligned.m8n8.x4.shared.b16 {%0,%1,%2,%3}, [%4];"
                            : "=r"(r0), "=r"(r1), "=r"(r2), "=r"(r3) : "r"(addr));
                        bf[p * 2][0] = r0; bf[p * 2][1] = r1;
                        bf[p * 2 + 1][0] = r2; bf[p * 2 + 1][1] = r3;
                    }
                    #pragma unroll
                    for (int mt = 0; mt < 4; mt++)
                        #pragma unroll
                        for (int nt = 0; nt < 8; nt++) {
                            asm volatile(
                                "mma.sync.aligned.m16n8k16.row.col.f32.f16.f16.f32 "
                                "{%0,%1,%2,%3}, {%4,%5,%6,%7}, {%8,%9}, {%0,%1,%2,%3};"
                                : "+f"(d[mt][nt][0]), "+f"(d[mt][nt][1]),
                                  "+f"(d[mt][nt][2]), "+f"(d[mt][nt][3])
                                : "r"(a[mt][0]), "r"(a[mt][1]), "r"(a[mt][2]), "r"(a[mt][3]),
                                  "r"(bf[nt][0]), "r"(bf[nt][1]));
                        }
                }
                __syncthreads();
            }

            // ---- epilogue for tile j (overlaps next tile's in-flight B) ----
            const int Cg  = (j & 127) * 2 + wc;
            const int gcb = gc0 + wc * 64;

            float p0[4] = {0.0f, 0.0f, 0.0f, 0.0f};
            float p1[4] = {0.0f, 0.0f, 0.0f, 0.0f};
            #pragma unroll
            for (int nt = 0; nt < 8; nt++) {
                int gcol = gcb + nt * 8 + 2 * tig;
                float2 bi = *(const float2*)(b_in + gcol);
                float2 gt = *(const float2*)(g_gate + gcol);
                #pragma unroll
                for (int mt = 0; mt < 4; mt++) {
                    p0[mt] += tanh_fast(d[mt][nt][0] + bi.x) * gt.x
                            + tanh_fast(d[mt][nt][1] + bi.y) * gt.y;
                    p1[mt] += tanh_fast(d[mt][nt][2] + bi.x) * gt.x
                            + tanh_fast(d[mt][nt][3] + bi.y) * gt.y;
                }
            }
            #pragma unroll
            for (int off = 1; off <= 2; off <<= 1) {
                #pragma unroll
                for (int mt = 0; mt < 4; mt++) {
                    p0[mt] += __shfl_xor_sync(0xffffffffu, p0[mt], off);
                    p1[mt] += __shfl_xor_sync(0xffffffffu, p1[mt], off);
                }
            }
            if (tig == 0) {
                float bo = __ldg(b_out + Cg);
                #pragma unroll
                for (int mt = 0; mt < 4; mt++) {
                    int r0 = m0 + wr * 64 + mt * 16 + g;
                    out[r0 * V + Cg]       = p0[mt] + bo;
                    out[(r0 + 8) * V + Cg] = p1[mt] + bo;
                }
            }
        }
        i = jend;
    }
}

// ---------------------------------------------------------------------------
extern "C" void kernel_launch(void* const* d_in, const int* in_sizes, int n_in,
                              void* d_out, int out_size) {
    const float* data    = (const float*)d_in[0];
    const float* adj     = (const float*)d_in[1];
    const float* neurons = (const float*)d_in[2];
    const float* w_in    = (const float*)d_in[3];
    const float* b_in    = (const float*)d_in[4];
    const float* w_out   = (const float*)d_in[5];
    const float* b_out   = (const float*)d_in[6];
    // d_in[7] = perm: analytic, never read.

    float* outp = (float*)d_out;
    int adj_off = out_size - N_SAMP * V;   // V*V = 65536
    float* out_main = outp + (adj_off > 0 ? adj_off : 0);

    prep_kernel<<<2048, 256>>>((const float4*)data, adj, neurons, w_in, w_out,
                               (float4*)outp);

    cudaFuncSetAttribute(fused_mma_kernel,
                         cudaFuncAttributeMaxDynamicSharedMemorySize, SMEM_TOTAL);
    fused_mma_kernel<<<GRID_MAIN, 128, SMEM_TOTAL>>>(b_in, b_out, out_main);
}

// round 9
// speedup vs baseline: 1.1522x; 1.1522x over previous
#include <cuda_runtime.h>
#include <cuda_fp16.h>
#include <cstdint>

#define N_SAMP 4096
#define V 256
#define VM1 255
#define NH 64
#define NCOLS (V * NH)   // 16384

__device__ __half g_Ah[N_SAMP * V];   // data as fp16 [4096][256]
__device__ __half g_Bh[NCOLS * V];    // B^T: [gc][j]
__device__ float  g_gate[NCOLS];      // neurons[h,c]*w_out[c,h]

__device__ __forceinline__ uint32_t smem_u32(const void* p) {
    uint32_t a;
    asm("{ .reg .u64 t; cvta.to.shared.u64 t, %1; cvt.u32.u64 %0, t; }" : "=r"(a) : "l"(p));
    return a;
}
__device__ __forceinline__ float tanh_fast(float x) {
    float y; asm("tanh.approx.f32 %0, %1;" : "=f"(y) : "f"(x)); return y;
}
#define CP_ASYNC16(dst_u32, src_ptr) \
    asm volatile("cp.async.cg.shared.global [%0], [%1], 16;" :: "r"(dst_u32), "l"(src_ptr) : "memory")
#define CP_COMMIT() asm volatile("cp.async.commit_group;" ::: "memory")

// ---------------------------------------------------------------------------
// Merged prep (unchanged)
// ---------------------------------------------------------------------------
__global__ __launch_bounds__(256) void prep_kernel(
    const float4* __restrict__ data4,
    const float*  __restrict__ adj,
    const float*  __restrict__ neurons,
    const float*  __restrict__ w_in,
    const float*  __restrict__ w_out,
    float4* __restrict__ out_adj4)
{
    __shared__ float s[64][65];
    __shared__ float adjv[64];
    const int tid = threadIdx.x;

    if (blockIdx.x < 1024) {
        int idx = blockIdx.x * 256 + tid;
        if (idx < (N_SAMP * V) / 4) {
            float4 v = data4[idx];
            __half2* dst = (__half2*)(g_Ah + idx * 4);
            dst[0] = __floats2half2_rn(v.x, v.y);
            dst[1] = __floats2half2_rn(v.z, v.w);
        }
        if (idx < (V * V) / 4) out_adj4[idx] = ((const float4*)adj)[idx];
        if (idx < NCOLS / 4) {
            int gc = idx * 4;
            int c = gc >> 6, h = gc & 63;
            float4 g;
            g.x = neurons[(h + 0) * V + c] * w_out[gc + 0];
            g.y = neurons[(h + 1) * V + c] * w_out[gc + 1];
            g.z = neurons[(h + 2) * V + c] * w_out[gc + 2];
            g.w = neurons[(h + 3) * V + c] * w_out[gc + 3];
            *(float4*)(g_gate + gc) = g;
        }
    } else {
        const int bid = blockIdx.x - 1024;
        const int c   = bid >> 2;
        const int jb  = bid & 3;
        const int h   = tid & 63;
        const int kk4 = tid >> 6;

        if (tid < 64) {
            int j = jb * 64 + tid;
            adjv[tid] = (j == c) ? 0.0f : adj[j * V + c];
        }
        #pragma unroll
        for (int jj0 = 0; jj0 < 64; jj0 += 4) {
            int jj = jj0 + kk4;
            int j  = jb * 64 + jj;
            float w = 0.0f;
            if (j != c) {
                int k = j - (j > c ? 1 : 0);
                w = w_in[(c * VM1 + k) * NH + h];
            }
            s[jj][h] = w;
        }
        __syncthreads();
        #pragma unroll
        for (int h0 = 0; h0 < 64; h0 += 4) {
            int hh = h0 + (tid >> 6);
            int jj = tid & 63;
            float w = s[jj][hh] * adjv[jj];
            g_Bh[(c * 64 + hh) * V + jb * 64 + jj] = __float2half_rn(w);
        }
    }
}

// ---------------------------------------------------------------------------
// Fused GEMM (mma.sync m16n8k16 fp16->fp32) + tanh/gate/h-reduce epilogue.
// CTA: 128x128, 4 warps as 2x2, warp tile 64x64. BK=64, 3-stage cp.async
// pipeline, ONE __syncthreads per stage. 128 threads, 2 CTAs/SM.
// ---------------------------------------------------------------------------
#define BK 64
#define A_STAGE_BYTES 16384
#define STAGE_BYTES 32768                 // A 16KB + B 16KB
#define NSTAGE 3
#define SMEM_TOTAL (NSTAGE * STAGE_BYTES) // 96KB

__device__ __forceinline__ void prefetch_stage(uint32_t sbuf, int m0, int gc0,
                                               int k0, int ldr, int ldq) {
    uint32_t sa = sbuf, sB = sbuf + A_STAGE_BYTES;
    #pragma unroll
    for (int i = 0; i < 8; i++) {
        int r = ldr + i * 16;
        uint32_t dsw = (uint32_t)(r * 128 + ((ldq ^ (r & 7)) << 4));
        CP_ASYNC16(sa + dsw, g_Ah + (m0 + r) * V + k0 + ldq * 8);
        CP_ASYNC16(sB + dsw, g_Bh + (gc0 + r) * V + k0 + ldq * 8);
    }
}

__global__ __launch_bounds__(128, 2)
void fused_mma_kernel(const float* __restrict__ b_in,
                      const float* __restrict__ b_out,
                      float* __restrict__ out) {
    extern __shared__ __align__(16) char smem[];
    const uint32_t sb = smem_u32(smem);

    const int tid  = threadIdx.x;
    const int wid  = tid >> 5;
    const int lane = tid & 31;
    const int wr   = wid & 1;
    const int wc   = wid >> 1;
    const int ldr  = tid >> 3;
    const int ldq  = tid & 7;
    const int g    = lane >> 2;
    const int tig  = lane & 3;

    const int m0  = blockIdx.y * 128;
    const int gc0 = blockIdx.x * 128;

    float d[4][8][4];
    #pragma unroll
    for (int mt = 0; mt < 4; mt++)
        #pragma unroll
        for (int nt = 0; nt < 8; nt++)
            #pragma unroll
            for (int v = 0; v < 4; v++) d[mt][nt][v] = 0.0f;

    // ---- preamble: prefetch stages 0 and 1 (two commit groups) ----
    prefetch_stage(sb,               m0, gc0, 0 * BK, ldr, ldq);
    CP_COMMIT();
    prefetch_stage(sb + STAGE_BYTES, m0, gc0, 1 * BK, ldr, ldq);
    CP_COMMIT();

    #pragma unroll
    for (int t = 0; t < 4; t++) {
        // wait for stage t, then single barrier
        if (t < 3) asm volatile("cp.async.wait_group 1;" ::: "memory");
        else       asm volatile("cp.async.wait_group 0;" ::: "memory");
        __syncthreads();

        // prefetch stage t+2 into buf (t+2)%3 (safe: last read at stage t-1,
        // all threads past it due to the barrier above)
        if (t + 2 <= 3) {
            prefetch_stage(sb + (uint32_t)(((t + 2) % NSTAGE) * STAGE_BYTES),
                           m0, gc0, (t + 2) * BK, ldr, ldq);
            CP_COMMIT();
        }

        const uint32_t sa = sb + (uint32_t)((t % NSTAGE) * STAGE_BYTES);
        const uint32_t sB = sa + A_STAGE_BYTES;

        #pragma unroll
        for (int ks = 0; ks < 4; ks++) {
            uint32_t a[4][4];
            #pragma unroll
            for (int mt = 0; mt < 4; mt++) {
                int r = wr * 64 + mt * 16 + (lane & 15);
                int q = ks * 2 + (lane >> 4);
                uint32_t addr = sa + r * 128 + ((q ^ (r & 7)) << 4);
                asm volatile("ldmatrix.sync.aligned.m8n8.x4.shared.b16 {%0,%1,%2,%3}, [%4];"
                    : "=r"(a[mt][0]), "=r"(a[mt][1]), "=r"(a[mt][2]), "=r"(a[mt][3])
                    : "r"(addr));
            }
            uint32_t bf[8][2];
            #pragma unroll
            for (int p = 0; p < 4; p++) {
                int r = wc * 64 + p * 16 + (lane & 7) + ((lane >> 4) << 3);
                int q = ks * 2 + ((lane >> 3) & 1);
                uint32_t addr = sB + r * 128 + ((q ^ (r & 7)) << 4);
                uint32_t r0, r1, r2, r3;
                asm volatile("ldmatrix.sync.aligned.m8n8.x4.shared.b16 {%0,%1,%2,%3}, [%4];"
                    : "=r"(r0), "=r"(r1), "=r"(r2), "=r"(r3) : "r"(addr));
                bf[p * 2][0] = r0; bf[p * 2][1] = r1;
                bf[p * 2 + 1][0] = r2; bf[p * 2 + 1][1] = r3;
            }
            #pragma unroll
            for (int mt = 0; mt < 4; mt++)
                #pragma unroll
                for (int nt = 0; nt < 8; nt++) {
                    asm volatile(
                        "mma.sync.aligned.m16n8k16.row.col.f32.f16.f16.f32 "
                        "{%0,%1,%2,%3}, {%4,%5,%6,%7}, {%8,%9}, {%0,%1,%2,%3};"
                        : "+f"(d[mt][nt][0]), "+f"(d[mt][nt][1]),
                          "+f"(d[mt][nt][2]), "+f"(d[mt][nt][3])
                        : "r"(a[mt][0]), "r"(a[mt][1]), "r"(a[mt][2]), "r"(a[mt][3]),
                          "r"(bf[nt][0]), "r"(bf[nt][1]));
                }
        }
    }

    // ---- epilogue: tanh, gate, reduce over h=64 within the warp ----
    const int Cg  = blockIdx.x * 2 + wc;
    const int gcb = gc0 + wc * 64;

    float p0[4] = {0.0f, 0.0f, 0.0f, 0.0f};
    float p1[4] = {0.0f, 0.0f, 0.0f, 0.0f};
    #pragma unroll
    for (int nt = 0; nt < 8; nt++) {
        int gcol = gcb + nt * 8 + 2 * tig;
        float2 bi = *(const float2*)(b_in + gcol);
        float2 gt = *(const float2*)(g_gate + gcol);
        #pragma unroll
        for (int mt = 0; mt < 4; mt++) {
            p0[mt] += tanh_fast(d[mt][nt][0] + bi.x) * gt.x
                    + tanh_fast(d[mt][nt][1] + bi.y) * gt.y;
            p1[mt] += tanh_fast(d[mt][nt][2] + bi.x) * gt.x
                    + tanh_fast(d[mt][nt][3] + bi.y) * gt.y;
        }
    }
    #pragma unroll
    for (int off = 1; off <= 2; off <<= 1) {
        #pragma unroll
        for (int mt = 0; mt < 4; mt++) {
            p0[mt] += __shfl_xor_sync(0xffffffffu, p0[mt], off);
            p1[mt] += __shfl_xor_sync(0xffffffffu, p1[mt], off);
        }
    }
    if (tig == 0) {
        float bo = __ldg(b_out + Cg);
        #pragma unroll
        for (int mt = 0; mt < 4; mt++) {
            int r0 = m0 + wr * 64 + mt * 16 + g;
            out[r0 * V + Cg]       = p0[mt] + bo;
            out[(r0 + 8) * V + Cg] = p1[mt] + bo;
        }
    }
}

// ---------------------------------------------------------------------------
extern "C" void kernel_launch(void* const* d_in, const int* in_sizes, int n_in,
                              void* d_out, int out_size) {
    const float* data    = (const float*)d_in[0];
    const float* adj     = (const float*)d_in[1];
    const float* neurons = (const float*)d_in[2];
    const float* w_in    = (const float*)d_in[3];
    const float* b_in    = (const float*)d_in[4];
    const float* w_out   = (const float*)d_in[5];
    const float* b_out   = (const float*)d_in[6];
    // d_in[7] = perm: analytic, never read.

    float* outp = (float*)d_out;
    int adj_off = out_size - N_SAMP * V;   // V*V = 65536
    float* out_main = outp + (adj_off > 0 ? adj_off : 0);

    prep_kernel<<<2048, 256>>>((const float4*)data, adj, neurons, w_in, w_out,
                               (float4*)outp);

    cudaFuncSetAttribute(fused_mma_kernel,
                         cudaFuncAttributeMaxDynamicSharedMemorySize, SMEM_TOTAL);
    dim3 grid(NCOLS / 128, N_SAMP / 128);
    fused_mma_kernel<<<grid, 128, SMEM_TOTAL>>>(b_in, b_out, out_main);
}